// round 2
// baseline (speedup 1.0000x reference)
#include <cuda_runtime.h>

#define EMB 64
#define IN_DIM 32
#define KDENSE 2048           // EMB * IN_DIM
#define KTOT 2112             // + EMB bias rows
#define MAX_NODES 50000
#define MAX_EDGES 150000

// Scratch (allocation-free rule: __device__ globals)
__device__ float g_W2T[KTOT * EMB];            // [k][e]
__device__ float g_aggr[MAX_NODES * EMB];      // residual + scatter accumulator
__device__ int   g_src[MAX_EDGES];
__device__ int   g_tgt[MAX_EDGES];
__device__ int   g_idx_is64;                   // 1 if edge_index buffer is int64

// ---------------------------------------------------------------------------
// Probe edge_index dtype: if int64 (values < 2^31, LE), odd int32 slots are 0.
__global__ void probe_idx_kernel(const int* __restrict__ ei32, int M) {
    int n = 2 * M;                 // int32 slots if int32; half of slots if int64
    int is64 = 1;
    for (int i = 1; i < 256 && i < n; i += 2) {
        if (ei32[i] != 0) { is64 = 0; break; }
    }
    g_idx_is64 = is64;
}

// Normalize edge_index into int arrays regardless of stored dtype.
__global__ void convert_idx_kernel(const void* __restrict__ eidx, int M) {
    int i = blockIdx.x * blockDim.x + threadIdx.x;
    if (i >= M) return;
    if (g_idx_is64) {
        const long long* p = (const long long*)eidx;
        g_src[i] = (int)p[i];
        g_tgt[i] = (int)p[M + i];
    } else {
        const int* p = (const int*)eidx;
        g_src[i] = p[i];
        g_tgt[i] = p[M + i];
    }
}

// ---------------------------------------------------------------------------
// W2T[k][e]: k<2048 -> W[(e*64+f)*32+d], f=k>>5, d=k&31 ; k>=2048 -> b[e*64+(k-2048)]
__global__ void prep_w_kernel(const float* __restrict__ W, const float* __restrict__ b) {
    int idx = blockIdx.x * blockDim.x + threadIdx.x;
    if (idx >= KTOT * EMB) return;
    int k = idx >> 6, e = idx & 63;
    float v;
    if (k < KDENSE) {
        int f = k >> 5, d = k & 31;
        v = W[(e * 64 + f) * 32 + d];
    } else {
        v = b[e * 64 + (k - KDENSE)];
    }
    g_W2T[idx] = v;
}

__global__ void init_aggr_kernel(const float* __restrict__ h, int n) {
    int i = blockIdx.x * blockDim.x + threadIdx.x;
    if (i < n) g_aggr[i] = h[i];
}

// ---------------------------------------------------------------------------
// Tile: 64 edges x 64 outputs per block, 256 threads, 4x4 microtile.
// A[m,k] = hjs[m][k>>5] * eas[m][k&31]; chunks 64..65 are the bias rows.
__global__ __launch_bounds__(256) void edge_msg_kernel(
    const float* __restrict__ h,
    const float* __restrict__ ea,
    int M)
{
    __shared__ float hjs[64][65];   // gathered h[tgt[m]]  (padded)
    __shared__ float eas[64][33];   // edge_attr tile      (padded)
    __shared__ float As[32][64];    // A chunk, [kk][m]
    __shared__ float Ws[32][64];    // W2T chunk, [kk][e]
    __shared__ int   srcs[64];

    const int tid = threadIdx.x;
    const int m0  = blockIdx.x * 64;

    if (tid < 64) {
        int gm = m0 + tid;
        srcs[tid] = (gm < M) ? g_src[gm] : -1;
    }
    #pragma unroll
    for (int i = 0; i < 16; i++) {                   // gather hj: 64x64
        int lin = tid + i * 256;
        int m = lin >> 6, e = lin & 63;
        int gm = m0 + m;
        float v = 0.f;
        if (gm < M) {
            int t = g_tgt[gm];
            v = h[(long long)t * 64 + e];
        }
        hjs[m][e] = v;
    }
    #pragma unroll
    for (int i = 0; i < 8; i++) {                    // edge_attr: 64x32
        int lin = tid + i * 256;
        int m = lin >> 5, d = lin & 31;
        int gm = m0 + m;
        eas[m][d] = (gm < M) ? ea[(long long)gm * 32 + d] : 0.f;
    }
    __syncthreads();

    const int ty = tid >> 4, tx = tid & 15;
    float acc[4][4] = {};

    for (int kc = 0; kc < 66; kc++) {
        #pragma unroll
        for (int i = 0; i < 8; i++) {
            int lin = tid + i * 256;                 // lin = kk*64 + m(or e)
            int kk = lin >> 6, m = lin & 63;
            float a;
            if (kc < 64) a = hjs[m][kc] * eas[m][kk];
            else         a = hjs[m][(kc - 64) * 32 + kk];
            As[kk][m] = a;
            Ws[kk][m] = g_W2T[kc * 2048 + lin];
        }
        __syncthreads();
        #pragma unroll
        for (int kk = 0; kk < 32; kk++) {
            float4 av = *(const float4*)&As[kk][ty * 4];
            float4 bv = *(const float4*)&Ws[kk][tx * 4];
            acc[0][0] += av.x * bv.x; acc[0][1] += av.x * bv.y;
            acc[0][2] += av.x * bv.z; acc[0][3] += av.x * bv.w;
            acc[1][0] += av.y * bv.x; acc[1][1] += av.y * bv.y;
            acc[1][2] += av.y * bv.z; acc[1][3] += av.y * bv.w;
            acc[2][0] += av.z * bv.x; acc[2][1] += av.z * bv.y;
            acc[2][2] += av.z * bv.z; acc[2][3] += av.z * bv.w;
            acc[3][0] += av.w * bv.x; acc[3][1] += av.w * bv.y;
            acc[3][2] += av.w * bv.z; acc[3][3] += av.w * bv.w;
        }
        __syncthreads();
    }

    #pragma unroll
    for (int i = 0; i < 4; i++) {
        int src = srcs[ty * 4 + i];
        if (src >= 0) {
            float* p = &g_aggr[(long long)src * 64 + tx * 4];
            atomicAdd(p + 0, acc[i][0]);
            atomicAdd(p + 1, acc[i][1]);
            atomicAdd(p + 2, acc[i][2]);
            atomicAdd(p + 3, acc[i][3]);
        }
    }
}

// ---------------------------------------------------------------------------
// LayerNorm over rows of g_aggr (already holds h + aggr). Warp per row.
__global__ void ln_kernel(const float* __restrict__ gamma,
                          const float* __restrict__ beta,
                          float* __restrict__ out, int N)
{
    int row  = blockIdx.x * 8 + (threadIdx.x >> 5);
    int lane = threadIdx.x & 31;
    if (row >= N) return;
    float x0 = g_aggr[row * 64 + lane];
    float x1 = g_aggr[row * 64 + 32 + lane];
    float s = x0 + x1;
    #pragma unroll
    for (int o = 16; o > 0; o >>= 1) s += __shfl_xor_sync(0xffffffffu, s, o);
    float mu = s * (1.f / 64.f);
    float d0 = x0 - mu, d1 = x1 - mu;
    float v = d0 * d0 + d1 * d1;
    #pragma unroll
    for (int o = 16; o > 0; o >>= 1) v += __shfl_xor_sync(0xffffffffu, v, o);
    float inv = rsqrtf(v * (1.f / 64.f) + 1e-5f);
    out[row * 64 + lane]      = d0 * inv * gamma[lane]      + beta[lane];
    out[row * 64 + 32 + lane] = d1 * inv * gamma[lane + 32] + beta[lane + 32];
}

// ---------------------------------------------------------------------------
extern "C" void kernel_launch(void* const* d_in, const int* in_sizes, int n_in,
                              void* d_out, int out_size) {
    // Positional defaults (setup_inputs dict order)
    const float* h     = (const float*)d_in[0];
    const float* ea    = (const float*)d_in[1];
    const float* W     = (const float*)d_in[2];
    const float* b     = (const float*)d_in[3];
    const float* gamma = (const float*)d_in[4];
    const float* beta  = (const float*)d_in[5];
    const void*  eidx  = d_in[6];

    // Override by element count (all sizes unique; gamma before beta for ties)
    int n64_seen = 0;
    for (int i = 0; i < n_in; i++) {
        switch (in_sizes[i]) {
            case 3200000: h    = (const float*)d_in[i]; break;
            case 4800000: ea   = (const float*)d_in[i]; break;
            case 131072:  W    = (const float*)d_in[i]; break;
            case 4096:    b    = (const float*)d_in[i]; break;
            case 300000:  eidx = d_in[i];               break;
            case 64:
                if (n64_seen++ == 0) gamma = (const float*)d_in[i];
                else                 beta  = (const float*)d_in[i];
                break;
            default: break;
        }
    }

    const int N = 50000;
    const int M = 150000;
    float* out = (float*)d_out;

    probe_idx_kernel<<<1, 1>>>((const int*)eidx, M);
    convert_idx_kernel<<<(M + 255) / 256, 256>>>(eidx, M);
    prep_w_kernel<<<(KTOT * EMB + 255) / 256, 256>>>(W, b);
    init_aggr_kernel<<<(N * EMB + 255) / 256, 256>>>(h, N * EMB);
    edge_msg_kernel<<<(M + 63) / 64, 256>>>(h, ea, M);
    ln_kernel<<<(N + 7) / 8, 256>>>(gamma, beta, out, N);
}

// round 3
// speedup vs baseline: 1.8776x; 1.8776x over previous
#include <cuda_runtime.h>

#define EMB 64
#define IN_DIM 32
#define NKV 2112              // (IN_DIM+1) * EMB  : V row pitch, d*64+e, d=32 -> bias
#define MAX_NODES 50000
#define MAX_EDGES 150000

// Scratch (__device__ globals; allocation-free rule)
__device__ float g_W3T[EMB * NKV];                 // [f][d*64+e]
__device__ float g_V[(size_t)MAX_NODES * NKV];     // per-node transformed features (~422MB)
__device__ float g_aggr[MAX_NODES * EMB];          // residual + scatter accumulator
__device__ int   g_src[MAX_EDGES];
__device__ int   g_tgt[MAX_EDGES];
__device__ int   g_idx_is64;

// ---------------------------------------------------------------------------
__global__ void probe_idx_kernel(const int* __restrict__ ei32, int M) {
    int n = 2 * M;
    int is64 = 1;
    for (int i = 1; i < 256 && i < n; i += 2)
        if (ei32[i] != 0) { is64 = 0; break; }
    g_idx_is64 = is64;
}

__global__ void convert_idx_kernel(const void* __restrict__ eidx, int M) {
    int i = blockIdx.x * blockDim.x + threadIdx.x;
    if (i >= M) return;
    if (g_idx_is64) {
        const long long* p = (const long long*)eidx;
        g_src[i] = (int)p[i];
        g_tgt[i] = (int)p[M + i];
    } else {
        const int* p = (const int*)eidx;
        g_src[i] = p[i];
        g_tgt[i] = p[M + i];
    }
}

// W3T[f][d*64+e] = W[(e*64+f)*32+d] for d<32 ; = b[e*64+f] for d==32
__global__ void prep_w_kernel(const float* __restrict__ W, const float* __restrict__ b) {
    int idx = blockIdx.x * blockDim.x + threadIdx.x;
    if (idx >= EMB * NKV) return;
    int f = idx / NKV, c = idx % NKV;
    int d = c >> 6, e = c & 63;
    g_W3T[idx] = (d < 32) ? W[(e * 64 + f) * 32 + d] : b[e * 64 + f];
}

__global__ void init_aggr_kernel(const float* __restrict__ h, int n) {
    int i = blockIdx.x * blockDim.x + threadIdx.x;
    if (i < n) g_aggr[i] = h[i];
}

// ---------------------------------------------------------------------------
// Stage 1: V = h @ W3T.  [N x 64] @ [64 x 2112].
// Block tile 128 nodes x 128 outputs, 256 threads, 8x8 microtile, K=64 whole.
__global__ __launch_bounds__(256) void node_v_kernel(const float* __restrict__ h, int N)
{
    __shared__ float Hs[64][129];   // [f][m], pad 129 -> conflict-free both ways
    __shared__ float Ws[64][129];   // [f][n]

    const int tid = threadIdx.x;
    const int m0  = blockIdx.x * 128;
    const int n0  = blockIdx.y * 128;

    #pragma unroll
    for (int i = 0; i < 32; i++) {               // H tile: 128m x 64f
        int lin = tid + i * 256;
        int m = lin >> 6, f = lin & 63;
        int gm = m0 + m;
        Hs[f][m] = (gm < N) ? h[gm * 64 + f] : 0.f;
    }
    #pragma unroll
    for (int i = 0; i < 32; i++) {               // W tile: 64f x 128n (coalesced)
        int lin = tid + i * 256;
        int f = lin >> 7, n = lin & 127;
        int gn = n0 + n;
        Ws[f][n] = (gn < NKV) ? g_W3T[f * NKV + gn] : 0.f;
    }
    __syncthreads();

    const int ty = tid >> 4, tx = tid & 15;      // m-dir, n-dir
    float acc[8][8] = {};

    #pragma unroll
    for (int f = 0; f < 64; f++) {
        float a[8], bb[8];
        #pragma unroll
        for (int i = 0; i < 8; i++) a[i]  = Hs[f][ty * 8 + i];
        #pragma unroll
        for (int j = 0; j < 8; j++) bb[j] = Ws[f][tx + 16 * j];
        #pragma unroll
        for (int i = 0; i < 8; i++)
            #pragma unroll
            for (int j = 0; j < 8; j++)
                acc[i][j] += a[i] * bb[j];
    }

    #pragma unroll
    for (int i = 0; i < 8; i++) {
        int gm = m0 + ty * 8 + i;
        if (gm >= N) continue;
        float* vrow = g_V + (size_t)gm * NKV;
        #pragma unroll
        for (int j = 0; j < 8; j++) {
            int gn = n0 + tx + 16 * j;
            if (gn < NKV) vrow[gn] = acc[i][j];
        }
    }
}

// ---------------------------------------------------------------------------
// Stage 2: warp per edge. msg[m,e] = sum_d ea[m,d]*V[tgt][d*64+e] + V[tgt][2048+e]
__global__ __launch_bounds__(256) void edge_msg_kernel(const float* __restrict__ ea, int M)
{
    int m    = blockIdx.x * 8 + (threadIdx.x >> 5);
    int lane = threadIdx.x & 31;
    if (m >= M) return;

    float eav = ea[(size_t)m * 32 + lane];
    int t = g_tgt[m], s = g_src[m];
    const float* Vt = g_V + (size_t)t * NKV;

    float acc0 = Vt[2048 + lane];        // bias row (d=32)
    float acc1 = Vt[2048 + 32 + lane];
    #pragma unroll
    for (int d = 0; d < 32; d++) {
        float a = __shfl_sync(0xffffffffu, eav, d);
        acc0 += a * Vt[d * 64 + lane];
        acc1 += a * Vt[d * 64 + 32 + lane];
    }
    atomicAdd(&g_aggr[s * 64 + lane],      acc0);
    atomicAdd(&g_aggr[s * 64 + 32 + lane], acc1);
}

// ---------------------------------------------------------------------------
__global__ void ln_kernel(const float* __restrict__ gamma,
                          const float* __restrict__ beta,
                          float* __restrict__ out, int N)
{
    int row  = blockIdx.x * 8 + (threadIdx.x >> 5);
    int lane = threadIdx.x & 31;
    if (row >= N) return;
    float x0 = g_aggr[row * 64 + lane];
    float x1 = g_aggr[row * 64 + 32 + lane];
    float s = x0 + x1;
    #pragma unroll
    for (int o = 16; o > 0; o >>= 1) s += __shfl_xor_sync(0xffffffffu, s, o);
    float mu = s * (1.f / 64.f);
    float d0 = x0 - mu, d1 = x1 - mu;
    float v = d0 * d0 + d1 * d1;
    #pragma unroll
    for (int o = 16; o > 0; o >>= 1) v += __shfl_xor_sync(0xffffffffu, v, o);
    float inv = rsqrtf(v * (1.f / 64.f) + 1e-5f);
    out[row * 64 + lane]      = d0 * inv * gamma[lane]      + beta[lane];
    out[row * 64 + 32 + lane] = d1 * inv * gamma[lane + 32] + beta[lane + 32];
}

// ---------------------------------------------------------------------------
extern "C" void kernel_launch(void* const* d_in, const int* in_sizes, int n_in,
                              void* d_out, int out_size) {
    const float* h     = (const float*)d_in[0];
    const float* ea    = (const float*)d_in[1];
    const float* W     = (const float*)d_in[2];
    const float* b     = (const float*)d_in[3];
    const float* gamma = (const float*)d_in[4];
    const float* beta  = (const float*)d_in[5];
    const void*  eidx  = d_in[6];

    int n64_seen = 0;
    for (int i = 0; i < n_in; i++) {
        switch (in_sizes[i]) {
            case 3200000: h    = (const float*)d_in[i]; break;
            case 4800000: ea   = (const float*)d_in[i]; break;
            case 131072:  W    = (const float*)d_in[i]; break;
            case 4096:    b    = (const float*)d_in[i]; break;
            case 300000:  eidx = d_in[i];               break;
            case 64:
                if (n64_seen++ == 0) gamma = (const float*)d_in[i];
                else                 beta  = (const float*)d_in[i];
                break;
            default: break;
        }
    }

    const int N = 50000;
    const int M = 150000;
    float* out = (float*)d_out;

    probe_idx_kernel<<<1, 1>>>((const int*)eidx, M);
    convert_idx_kernel<<<(M + 255) / 256, 256>>>(eidx, M);
    prep_w_kernel<<<(EMB * NKV + 255) / 256, 256>>>(W, b);
    init_aggr_kernel<<<(N * EMB + 255) / 256, 256>>>(h, N * EMB);

    dim3 g1((N + 127) / 128, (NKV + 127) / 128);   // 391 x 17
    node_v_kernel<<<g1, 256>>>(h, N);

    edge_msg_kernel<<<(M + 7) / 8, 256>>>(ea, M);
    ln_kernel<<<(N + 7) / 8, 256>>>(gamma, beta, out, N);
}

// round 4
// speedup vs baseline: 2.4211x; 1.2895x over previous
#include <cuda_runtime.h>

#define EMB 64
#define IN_DIM 32
#define NKV 2112              // (IN_DIM+1)*EMB : V row pitch, col = d*64+e, d=32 -> bias
#define MAX_NODES 50000
#define MAX_EDGES 150000
#define NBINS MAX_NODES
#define SCAN_NB ((NBINS + 255) / 256)

// Scratch (__device__ globals; allocation-free rule)
__device__ float g_W3T[EMB * NKV];                 // [f][d*64+e]
__device__ float g_V[(size_t)MAX_NODES * NKV];     // per-node transformed features
__device__ float g_aggr[MAX_NODES * EMB];          // residual + scatter accumulator
__device__ int   g_src[MAX_EDGES];
__device__ int   g_tgt[MAX_EDGES];
__device__ int   g_eord[MAX_EDGES];
__device__ int   g_cnt[NBINS];
__device__ int   g_off[NBINS];
__device__ int   g_bsum[SCAN_NB];
__device__ int   g_boff[SCAN_NB];
__device__ int   g_idx_is64;

// ---------------------------------------------------------------------------
__global__ void probe_idx_kernel(const int* __restrict__ ei32, int M) {
    int n = 2 * M;
    int is64 = 1;
    for (int i = 1; i < 256 && i < n; i += 2)
        if (ei32[i] != 0) { is64 = 0; break; }
    g_idx_is64 = is64;
}

__global__ void convert_idx_kernel(const void* __restrict__ eidx, int M) {
    int i = blockIdx.x * blockDim.x + threadIdx.x;
    if (i >= M) return;
    if (g_idx_is64) {
        const long long* p = (const long long*)eidx;
        g_src[i] = (int)p[i];
        g_tgt[i] = (int)p[M + i];
    } else {
        const int* p = (const int*)eidx;
        g_src[i] = p[i];
        g_tgt[i] = p[M + i];
    }
}

// W3T[f][d*64+e] = W[(e*64+f)*32+d] for d<32 ; = b[e*64+f] for d==32
__global__ void prep_w_kernel(const float* __restrict__ W, const float* __restrict__ b) {
    int idx = blockIdx.x * blockDim.x + threadIdx.x;
    if (idx >= EMB * NKV) return;
    int f = idx / NKV, c = idx % NKV;
    int d = c >> 6, e = c & 63;
    g_W3T[idx] = (d < 32) ? W[(e * 64 + f) * 32 + d] : b[e * 64 + f];
}

__global__ void init_aggr_kernel(const float* __restrict__ h, int n) {
    int i = blockIdx.x * blockDim.x + threadIdx.x;
    if (i < n) g_aggr[i] = h[i];
}

// ---------------------------------------------------------------------------
// Stage 1: V = h @ W3T.  [N x 64] @ [64 x 2112]. 128x128 tile, 256 threads.
// Microtile 8 rows x 8 cols; cols are 4 f32x2 pairs at n = 2*tx + 32*j.
__device__ __forceinline__ void fma2(unsigned long long& acc,
                                     unsigned long long a2,
                                     unsigned long long b2) {
    asm("fma.rn.f32x2 %0, %1, %2, %0;" : "+l"(acc) : "l"(a2), "l"(b2));
}

__global__ __launch_bounds__(256) void node_v_kernel(const float* __restrict__ h, int N)
{
    __shared__ float Hs[64][130];   // [f][m], even pitch for 8B alignment
    __shared__ float Ws[64][130];   // [f][n]

    const int tid = threadIdx.x;
    const int m0  = blockIdx.x * 128;
    const int n0  = blockIdx.y * 128;

    #pragma unroll
    for (int i = 0; i < 32; i++) {               // H tile: 128m x 64f
        int lin = tid + i * 256;
        int m = lin >> 6, f = lin & 63;
        int gm = m0 + m;
        Hs[f][m] = (gm < N) ? h[gm * 64 + f] : 0.f;
    }
    #pragma unroll
    for (int i = 0; i < 32; i++) {               // W tile: 64f x 128n (coalesced)
        int lin = tid + i * 256;
        int f = lin >> 7, n = lin & 127;
        int gn = n0 + n;
        Ws[f][n] = (gn < NKV) ? g_W3T[f * NKV + gn] : 0.f;
    }
    __syncthreads();

    const int ty = tid >> 4, tx = tid & 15;      // ty: m-dir, tx: n-pair dir
    unsigned long long acc[8][4];
    #pragma unroll
    for (int i = 0; i < 8; i++)
        #pragma unroll
        for (int j = 0; j < 4; j++) acc[i][j] = 0ull;

    #pragma unroll
    for (int f = 0; f < 64; f++) {
        unsigned long long a2[8], b2[4];
        #pragma unroll
        for (int i = 0; i < 8; i++) {
            float a = Hs[f][ty * 8 + i];
            asm("mov.b64 %0, {%1, %1};" : "=l"(a2[i]) : "r"(__float_as_uint(a)));
        }
        #pragma unroll
        for (int j = 0; j < 4; j++)
            b2[j] = *(const unsigned long long*)&Ws[f][2 * tx + 32 * j];
        #pragma unroll
        for (int i = 0; i < 8; i++)
            #pragma unroll
            for (int j = 0; j < 4; j++)
                fma2(acc[i][j], a2[i], b2[j]);
    }

    #pragma unroll
    for (int i = 0; i < 8; i++) {
        int gm = m0 + ty * 8 + i;
        if (gm >= N) continue;
        float* vrow = g_V + (size_t)gm * NKV;
        #pragma unroll
        for (int j = 0; j < 4; j++) {
            int gn = n0 + 2 * tx + 32 * j;
            if (gn < NKV) *(unsigned long long*)&vrow[gn] = acc[i][j];
        }
    }
}

// ---------------------------------------------------------------------------
// Counting sort of edges by tgt (hist -> hierarchical scan -> scatter).
__global__ void zero_cnt_kernel() {
    int i = blockIdx.x * blockDim.x + threadIdx.x;
    if (i < NBINS) g_cnt[i] = 0;
    if (i < SCAN_NB) g_bsum[i] = 0;
}

__global__ void hist_kernel(int M) {
    int i = blockIdx.x * blockDim.x + threadIdx.x;
    if (i < M) atomicAdd(&g_cnt[g_tgt[i]], 1);
}

__global__ void scanA_kernel() {                 // per-256 block local scan
    __shared__ int buf[256];
    int b = blockIdx.x, t = threadIdx.x;
    int i = b * 256 + t;
    int v = (i < NBINS) ? g_cnt[i] : 0;
    buf[t] = v; __syncthreads();
    #pragma unroll
    for (int o = 1; o < 256; o <<= 1) {
        int u = (t >= o) ? buf[t - o] : 0;
        __syncthreads();
        buf[t] += u;
        __syncthreads();
    }
    if (i < NBINS) g_off[i] = buf[t] - v;
    if (t == 255) g_bsum[b] = buf[255];
}

__global__ void scanB_kernel() {                 // scan of 196 block sums (1 block)
    __shared__ int buf[256];
    int t = threadIdx.x;
    int v = (t < SCAN_NB) ? g_bsum[t] : 0;
    buf[t] = v; __syncthreads();
    #pragma unroll
    for (int o = 1; o < 256; o <<= 1) {
        int u = (t >= o) ? buf[t - o] : 0;
        __syncthreads();
        buf[t] += u;
        __syncthreads();
    }
    if (t < SCAN_NB) g_boff[t] = buf[t] - v;
}

__global__ void scanC_kernel() {
    int i = blockIdx.x * blockDim.x + threadIdx.x;
    if (i < NBINS) g_off[i] += g_boff[i >> 8];
}

__global__ void scatter_kernel(int M) {
    int i = blockIdx.x * blockDim.x + threadIdx.x;
    if (i >= M) return;
    int pos = atomicAdd(&g_off[g_tgt[i]], 1);
    g_eord[pos] = i;
}

// ---------------------------------------------------------------------------
// Stage 2: warp per edge, edges sorted by tgt for V-row L1/L2 reuse.
__global__ __launch_bounds__(256) void edge_msg_kernel(const float* __restrict__ ea, int M)
{
    int w    = blockIdx.x * 8 + (threadIdx.x >> 5);
    int lane = threadIdx.x & 31;
    if (w >= M) return;
    int m = g_eord[w];

    float eav = ea[(size_t)m * 32 + lane];
    int t = g_tgt[m], s = g_src[m];
    const float* Vt = g_V + (size_t)t * NKV;

    float acc0 = Vt[2048 + lane];        // bias row (d=32)
    float acc1 = Vt[2048 + 32 + lane];
    #pragma unroll
    for (int d = 0; d < 32; d++) {
        float a = __shfl_sync(0xffffffffu, eav, d);
        acc0 += a * Vt[d * 64 + lane];
        acc1 += a * Vt[d * 64 + 32 + lane];
    }
    atomicAdd(&g_aggr[s * 64 + lane],      acc0);
    atomicAdd(&g_aggr[s * 64 + 32 + lane], acc1);
}

// ---------------------------------------------------------------------------
__global__ void ln_kernel(const float* __restrict__ gamma,
                          const float* __restrict__ beta,
                          float* __restrict__ out, int N)
{
    int row  = blockIdx.x * 8 + (threadIdx.x >> 5);
    int lane = threadIdx.x & 31;
    if (row >= N) return;
    float x0 = g_aggr[row * 64 + lane];
    float x1 = g_aggr[row * 64 + 32 + lane];
    float s = x0 + x1;
    #pragma unroll
    for (int o = 16; o > 0; o >>= 1) s += __shfl_xor_sync(0xffffffffu, s, o);
    float mu = s * (1.f / 64.f);
    float d0 = x0 - mu, d1 = x1 - mu;
    float v = d0 * d0 + d1 * d1;
    #pragma unroll
    for (int o = 16; o > 0; o >>= 1) v += __shfl_xor_sync(0xffffffffu, v, o);
    float inv = rsqrtf(v * (1.f / 64.f) + 1e-5f);
    out[row * 64 + lane]      = d0 * inv * gamma[lane]      + beta[lane];
    out[row * 64 + 32 + lane] = d1 * inv * gamma[lane + 32] + beta[lane + 32];
}

// ---------------------------------------------------------------------------
extern "C" void kernel_launch(void* const* d_in, const int* in_sizes, int n_in,
                              void* d_out, int out_size) {
    const float* h     = (const float*)d_in[0];
    const float* ea    = (const float*)d_in[1];
    const float* W     = (const float*)d_in[2];
    const float* b     = (const float*)d_in[3];
    const float* gamma = (const float*)d_in[4];
    const float* beta  = (const float*)d_in[5];
    const void*  eidx  = d_in[6];

    int n64_seen = 0;
    for (int i = 0; i < n_in; i++) {
        switch (in_sizes[i]) {
            case 3200000: h    = (const float*)d_in[i]; break;
            case 4800000: ea   = (const float*)d_in[i]; break;
            case 131072:  W    = (const float*)d_in[i]; break;
            case 4096:    b    = (const float*)d_in[i]; break;
            case 300000:  eidx = d_in[i];               break;
            case 64:
                if (n64_seen++ == 0) gamma = (const float*)d_in[i];
                else                 beta  = (const float*)d_in[i];
                break;
            default: break;
        }
    }

    const int N = 50000;
    const int M = 150000;
    float* out = (float*)d_out;

    probe_idx_kernel<<<1, 1>>>((const int*)eidx, M);                 // 1
    convert_idx_kernel<<<(M + 255) / 256, 256>>>(eidx, M);           // 2
    prep_w_kernel<<<(EMB * NKV + 255) / 256, 256>>>(W, b);           // 3

    dim3 g1((N + 127) / 128, (NKV + 127) / 128);
    node_v_kernel<<<g1, 256>>>(h, N);                                // 4 (profiled slot)

    init_aggr_kernel<<<(N * EMB + 255) / 256, 256>>>(h, N * EMB);    // 5
    zero_cnt_kernel<<<(NBINS + 255) / 256, 256>>>();
    hist_kernel<<<(M + 255) / 256, 256>>>(M);
    scanA_kernel<<<SCAN_NB, 256>>>();
    scanB_kernel<<<1, 256>>>();
    scanC_kernel<<<(NBINS + 255) / 256, 256>>>();
    scatter_kernel<<<(M + 255) / 256, 256>>>(M);

    edge_msg_kernel<<<(M + 7) / 8, 256>>>(ea, M);
    ln_kernel<<<(N + 7) / 8, 256>>>(gamma, beta, out, N);
}